// round 1
// baseline (speedup 1.0000x reference)
#include <cuda_runtime.h>
#include <math.h>

#define N_FFT 8192
#define LOG_N 13
#define SEQ   4096
#define BATCH 8
#define MD    4
#define ORDER 256
#define INPUT 256
#define HID   512
#define MSZ   1280
#define FFT_T 512   // threads per FFT block

// ---------------- scratch (static device globals; no allocation) -------------
__device__ float  g_u  [32 * SEQ];              // relu(x@Wu^T+b), [b*4+d][t]
__device__ float2 g_tw [N_FFT / 2];             // forward twiddles e^{-2pi i k/N}
__device__ float  g_Ure[32 * N_FFT];            // spectra of u (bit-rev order)
__device__ float  g_Uim[32 * N_FFT];
__device__ float  g_Hre[ORDER * N_FFT];         // spectra of H (bit-rev order)
__device__ float  g_Him[ORDER * N_FFT];
__device__ float  g_Gre[HID * MD * N_FFT];      // G[h,d,k] = sum_o Wh*Hspec
__device__ float  g_Gim[HID * MD * N_FFT];
__device__ float  g_hx [BATCH * HID * SEQ];     // x-part of h (pre-relu), [b][h][t]

// ---------------- twiddle table ----------------------------------------------
__global__ void twiddle_kernel() {
    int k = blockIdx.x * blockDim.x + threadIdx.x;
    if (k < N_FFT / 2) {
        float s, c;
        sincospif(-(float)k / (float)(N_FFT / 2), &s, &c);  // -2*pi*k/N = pi * (-k/(N/2))
        g_tw[k] = make_float2(c, s);
    }
}

// ---------------- u = relu(x @ Wu^T + b) --------------------------------------
__global__ void u_kernel(const float* __restrict__ x,
                         const float* __restrict__ Wu_w,
                         const float* __restrict__ Wu_b) {
    int gw   = (blockIdx.x * blockDim.x + threadIdx.x) >> 5;  // one warp per (b,t)
    int lane = threadIdx.x & 31;
    if (gw >= BATCH * SEQ) return;
    int b = gw >> 12, t = gw & (SEQ - 1);
    const float* xp = x + (size_t)(b * SEQ + t) * INPUT;
    float a0 = 0.f, a1 = 0.f, a2 = 0.f, a3 = 0.f;
    #pragma unroll
    for (int i = lane; i < INPUT; i += 32) {
        float xv = xp[i];
        a0 = fmaf(xv, __ldg(&Wu_w[0 * INPUT + i]), a0);
        a1 = fmaf(xv, __ldg(&Wu_w[1 * INPUT + i]), a1);
        a2 = fmaf(xv, __ldg(&Wu_w[2 * INPUT + i]), a2);
        a3 = fmaf(xv, __ldg(&Wu_w[3 * INPUT + i]), a3);
    }
    #pragma unroll
    for (int off = 16; off; off >>= 1) {
        a0 += __shfl_down_sync(0xffffffffu, a0, off);
        a1 += __shfl_down_sync(0xffffffffu, a1, off);
        a2 += __shfl_down_sync(0xffffffffu, a2, off);
        a3 += __shfl_down_sync(0xffffffffu, a3, off);
    }
    if (lane == 0) {
        g_u[(b * 4 + 0) * SEQ + t] = fmaxf(a0 + Wu_b[0], 0.f);
        g_u[(b * 4 + 1) * SEQ + t] = fmaxf(a1 + Wu_b[1], 0.f);
        g_u[(b * 4 + 2) * SEQ + t] = fmaxf(a2 + Wu_b[2], 0.f);
        g_u[(b * 4 + 3) * SEQ + t] = fmaxf(a3 + Wu_b[3], 0.f);
    }
}

// ---------------- FFT cores (shared memory, radix-2) -------------------------
// Forward: DIF (Gentleman-Sande), natural-order input -> bit-reversed output.
__device__ __forceinline__ void fft_dif(float* sre, float* sim, int tid) {
    for (int s = LOG_N - 1; s >= 0; --s) {
        int m = 1 << s;
        #pragma unroll
        for (int r = 0; r < (N_FFT / 2) / FFT_T; ++r) {
            int k  = tid + r * FFT_T;
            int j  = k & (m - 1);
            int i0 = ((k >> s) << (s + 1)) + j;
            int i1 = i0 + m;
            float2 w = g_tw[j << (LOG_N - 1 - s)];
            float ar = sre[i0], ai = sim[i0];
            float br = sre[i1], bi = sim[i1];
            sre[i0] = ar + br;
            sim[i0] = ai + bi;
            float dr = ar - br, di = ai - bi;
            sre[i1] = dr * w.x - di * w.y;
            sim[i1] = dr * w.y + di * w.x;
        }
        __syncthreads();
    }
}

// Inverse: DIT (Cooley-Tukey) with conjugate twiddles,
// bit-reversed input -> natural-order output, scaled by N (divide later).
__device__ __forceinline__ void fft_dit_inv(float* sre, float* sim, int tid) {
    for (int s = 0; s < LOG_N; ++s) {
        int m = 1 << s;
        #pragma unroll
        for (int r = 0; r < (N_FFT / 2) / FFT_T; ++r) {
            int k  = tid + r * FFT_T;
            int j  = k & (m - 1);
            int i0 = ((k >> s) << (s + 1)) + j;
            int i1 = i0 + m;
            float2 w = g_tw[j << (LOG_N - 1 - s)];  // use conj(w)
            float br = sre[i1], bi = sim[i1];
            float vr = br * w.x + bi * w.y;
            float vi = bi * w.x - br * w.y;
            float ar = sre[i0], ai = sim[i0];
            sre[i0] = ar + vr;
            sim[i0] = ai + vi;
            sre[i1] = ar - vr;
            sim[i1] = ai - vi;
        }
        __syncthreads();
    }
}

// Forward FFT of real length-4096 rows, zero-padded to 8192.
// mode 0: rows of g_u -> g_U spectra (32 rows). mode 1: rows of H -> g_H spectra (256 rows).
__global__ void fft_fwd_kernel(const float* __restrict__ Hin, int mode) {
    extern __shared__ float smem[];
    float* sre = smem;
    float* sim = smem + N_FFT;
    int row = blockIdx.x;
    int tid = threadIdx.x;
    const float* in = (mode == 0) ? (g_u + (size_t)row * SEQ) : (Hin + (size_t)row * SEQ);
    float* outre = (mode == 0) ? (g_Ure + (size_t)row * N_FFT) : (g_Hre + (size_t)row * N_FFT);
    float* outim = (mode == 0) ? (g_Uim + (size_t)row * N_FFT) : (g_Him + (size_t)row * N_FFT);

    for (int t = tid; t < N_FFT; t += FFT_T) {
        sre[t] = (t < SEQ) ? in[t] : 0.f;
        sim[t] = 0.f;
    }
    __syncthreads();
    fft_dif(sre, sim, tid);
    for (int t = tid; t < N_FFT; t += FFT_T) {
        outre[t] = sre[t];
        outim[t] = sim[t];
    }
}

// ---------------- G[h,d,k] = sum_o Wh[h, d*256+o] * Hspec[o,k] ----------------
__global__ void gbuild_kernel(const float* __restrict__ Wh_w) {
    __shared__ float sA [16][65];   // [oo][hh]
    __shared__ float sBr[16][68];   // [oo][kk]
    __shared__ float sBi[16][68];
    int d  = blockIdx.z;
    int h0 = blockIdx.y * 64;
    int k0 = blockIdx.x * 64;
    int tid = threadIdx.x;
    int tx = tid & 15, ty = tid >> 4;
    float accr[4][4] = {}, acci[4][4] = {};

    for (int o0 = 0; o0 < ORDER; o0 += 16) {
        #pragma unroll
        for (int r = 0; r < 4; ++r) {
            int e = tid + r * 256;
            int hh = e >> 4, oo = e & 15;
            sA[oo][hh] = Wh_w[(size_t)(h0 + hh) * MSZ + d * ORDER + o0 + oo];
        }
        #pragma unroll
        for (int r = 0; r < 4; ++r) {
            int e = tid + r * 256;
            int oo = e >> 6, kk = e & 63;
            size_t src = (size_t)(o0 + oo) * N_FFT + k0 + kk;
            sBr[oo][kk] = g_Hre[src];
            sBi[oo][kk] = g_Him[src];
        }
        __syncthreads();
        #pragma unroll
        for (int oo = 0; oo < 16; ++oo) {
            float a[4], br[4], bi[4];
            #pragma unroll
            for (int i = 0; i < 4; ++i) a[i] = sA[oo][ty * 4 + i];
            #pragma unroll
            for (int j = 0; j < 4; ++j) { br[j] = sBr[oo][tx * 4 + j]; bi[j] = sBi[oo][tx * 4 + j]; }
            #pragma unroll
            for (int i = 0; i < 4; ++i)
                #pragma unroll
                for (int j = 0; j < 4; ++j) {
                    accr[i][j] = fmaf(a[i], br[j], accr[i][j]);
                    acci[i][j] = fmaf(a[i], bi[j], acci[i][j]);
                }
        }
        __syncthreads();
    }
    #pragma unroll
    for (int i = 0; i < 4; ++i)
        #pragma unroll
        for (int j = 0; j < 4; ++j) {
            int h = h0 + ty * 4 + i;
            int k = k0 + tx * 4 + j;
            size_t dst = (size_t)(h * MD + d) * N_FFT + k;
            g_Gre[dst] = accr[i][j];
            g_Gim[dst] = acci[i][j];
        }
}

// ---------------- hx[b,h,t] = sum_i Wh[h,1024+i]*x[b,t,i] + Wh_b[h] -----------
__global__ void hx_gemm_kernel(const float* __restrict__ x,
                               const float* __restrict__ Wh_w,
                               const float* __restrict__ Wh_b) {
    __shared__ float sA[16][65];    // [kk][hh]  Wh x-part
    __shared__ float sB[16][132];   // [kk][tt]  x transposed tile
    int b  = blockIdx.z;
    int h0 = blockIdx.y * 64;
    int t0 = blockIdx.x * 128;
    int tid = threadIdx.x;
    int tx = tid & 15, ty = tid >> 4;
    float acc[4][8] = {};

    for (int i0 = 0; i0 < INPUT; i0 += 16) {
        #pragma unroll
        for (int r = 0; r < 4; ++r) {
            int e = tid + r * 256;
            int hh = e >> 4, kk = e & 15;
            sA[kk][hh] = Wh_w[(size_t)(h0 + hh) * MSZ + MD * ORDER + i0 + kk];
        }
        #pragma unroll
        for (int r = 0; r < 8; ++r) {
            int e = tid + r * 256;
            int tt = e >> 4, kk = e & 15;
            sB[kk][tt] = x[(size_t)(b * SEQ + t0 + tt) * INPUT + i0 + kk];
        }
        __syncthreads();
        #pragma unroll
        for (int kk = 0; kk < 16; ++kk) {
            float a[4], bb[8];
            #pragma unroll
            for (int i = 0; i < 4; ++i) a[i] = sA[kk][ty * 4 + i];
            #pragma unroll
            for (int j = 0; j < 8; ++j) bb[j] = sB[kk][tx * 8 + j];
            #pragma unroll
            for (int i = 0; i < 4; ++i)
                #pragma unroll
                for (int j = 0; j < 8; ++j)
                    acc[i][j] = fmaf(a[i], bb[j], acc[i][j]);
        }
        __syncthreads();
    }
    #pragma unroll
    for (int i = 0; i < 4; ++i) {
        int h = h0 + ty * 4 + i;
        float bias = Wh_b[h];
        #pragma unroll
        for (int j = 0; j < 8; ++j) {
            int t = t0 + tx * 8 + j;
            g_hx[(size_t)(b * HID + h) * SEQ + t] = acc[i][j] + bias;
        }
    }
}

// ---------------- P = sum_d G*U ; iFFT ; h = relu(P/N + hx) (in-place) --------
__global__ void pifft_kernel() {
    extern __shared__ float smem[];
    float* sre = smem;
    float* sim = smem + N_FFT;
    int h = blockIdx.x >> 3;
    int b = blockIdx.x & 7;
    int tid = threadIdx.x;

    const float* Ur = g_Ure + (size_t)b * MD * N_FFT;
    const float* Ui = g_Uim + (size_t)b * MD * N_FFT;
    const float* Gr = g_Gre + (size_t)h * MD * N_FFT;
    const float* Gi = g_Gim + (size_t)h * MD * N_FFT;

    #pragma unroll
    for (int r = 0; r < N_FFT / FFT_T; ++r) {
        int k = tid + r * FFT_T;
        float pr = 0.f, pi = 0.f;
        #pragma unroll
        for (int d = 0; d < MD; ++d) {
            float ur = Ur[d * N_FFT + k], ui = Ui[d * N_FFT + k];
            float gr = Gr[d * N_FFT + k], gi = Gi[d * N_FFT + k];
            pr += ur * gr - ui * gi;
            pi += ur * gi + ui * gr;
        }
        sre[k] = pr;
        sim[k] = pi;
    }
    __syncthreads();
    fft_dit_inv(sre, sim, tid);

    float* hxp = g_hx + (size_t)(b * HID + h) * SEQ;
    const float inv_n = 1.0f / (float)N_FFT;
    for (int t = tid; t < SEQ; t += FFT_T) {
        float v = sre[t] * inv_n + hxp[t];
        hxp[t] = fmaxf(v, 0.f);
    }
}

// ---------------- transpose [b][h][t] -> out [b][t][h] ------------------------
__global__ void transpose_kernel(float* __restrict__ out) {
    __shared__ float tile[32][33];
    int b  = blockIdx.z;
    int h0 = blockIdx.y * 32;
    int t0 = blockIdx.x * 32;
    int tx = threadIdx.x, ty = threadIdx.y;  // 32 x 8
    #pragma unroll
    for (int r = 0; r < 32; r += 8)
        tile[ty + r][tx] = g_hx[(size_t)(b * HID + h0 + ty + r) * SEQ + t0 + tx];
    __syncthreads();
    #pragma unroll
    for (int r = 0; r < 32; r += 8)
        out[(size_t)(b * SEQ + t0 + ty + r) * HID + h0 + tx] = tile[tx][ty + r];
}

// ---------------- h[:, -1, :] appended after h ---------------------------------
__global__ void last_kernel(float* __restrict__ out) {
    int i = blockIdx.x * blockDim.x + threadIdx.x;  // i = b*512 + h
    if (i < BATCH * HID)
        out[(size_t)BATCH * SEQ * HID + i] = g_hx[(size_t)i * SEQ + (SEQ - 1)];
}

// ---------------- launch -------------------------------------------------------
extern "C" void kernel_launch(void* const* d_in, const int* in_sizes, int n_in,
                              void* d_out, int out_size) {
    const float* x    = (const float*)d_in[0];
    const float* Wu_w = (const float*)d_in[1];
    const float* Wu_b = (const float*)d_in[2];
    const float* Wh_w = (const float*)d_in[3];
    const float* Wh_b = (const float*)d_in[4];
    const float* H    = (const float*)d_in[5];
    float* out = (float*)d_out;

    const int fft_smem = 2 * N_FFT * (int)sizeof(float);  // 64 KB
    cudaFuncSetAttribute(fft_fwd_kernel, cudaFuncAttributeMaxDynamicSharedMemorySize, fft_smem);
    cudaFuncSetAttribute(pifft_kernel,   cudaFuncAttributeMaxDynamicSharedMemorySize, fft_smem);

    twiddle_kernel<<<8, 512>>>();
    u_kernel<<<(BATCH * SEQ * 32) / 256, 256>>>(x, Wu_w, Wu_b);

    fft_fwd_kernel<<<32,  FFT_T, fft_smem>>>(nullptr, 0);   // u spectra
    fft_fwd_kernel<<<ORDER, FFT_T, fft_smem>>>(H, 1);       // H spectra

    gbuild_kernel<<<dim3(N_FFT / 64, HID / 64, MD), 256>>>(Wh_w);
    hx_gemm_kernel<<<dim3(SEQ / 128, HID / 64, BATCH), 256>>>(x, Wh_w, Wh_b);

    pifft_kernel<<<HID * BATCH, FFT_T, fft_smem>>>();

    transpose_kernel<<<dim3(SEQ / 32, HID / 32, BATCH), dim3(32, 8)>>>(out);
    if (out_size >= BATCH * SEQ * HID + BATCH * HID)
        last_kernel<<<8, 512>>>(out);
}

// round 2
// speedup vs baseline: 1.6586x; 1.6586x over previous
#include <cuda_runtime.h>
#include <math.h>

#define SEQ   4096
#define BATCH 8
#define MD    4
#define ORDER 256
#define INPUT 256
#define HID   512
#define MSZ   1280
#define NH    4096      // complex FFT size (= 8192/2), real-FFT packing
#define LOGH  12
#define KS    4160      // spectrum row stride: 4096 bitrev slots + nyquist + pad
#define FFT_T 512

// ---------------- scratch (static device globals; zero-init, no allocation) ---
__device__ float  g_u  [32 * SEQ];
__device__ float2 g_tw [NH];            // e^{-2*pi*i*k/8192}, k = 0..4095
__device__ float  g_Ure[32 * KS];
__device__ float  g_Uim[32 * KS];
__device__ float  g_Hre[ORDER * KS];
__device__ float  g_Him[ORDER * KS];
__device__ float  g_Gre[HID * MD * KS];
__device__ float  g_Gim[HID * MD * KS];
__device__ float  g_hx [BATCH * HID * SEQ];  // x-part of h (pre-relu), [b][h][t]

__device__ __forceinline__ int rev12(int x) { return (int)(__brev((unsigned)x) >> 20); }

// ---------------- twiddle table ------------------------------------------------
__global__ void twiddle_kernel() {
    int k = blockIdx.x * blockDim.x + threadIdx.x;
    if (k < NH) {
        float s, c;
        sincospif(-(float)k / 4096.0f, &s, &c);   // e^{-2 pi i k / 8192}
        g_tw[k] = make_float2(c, s);
    }
}

// ---------------- u = relu(x @ Wu^T + b) ----------------------------------------
__global__ void u_kernel(const float* __restrict__ x,
                         const float* __restrict__ Wu_w,
                         const float* __restrict__ Wu_b) {
    int gw   = (blockIdx.x * blockDim.x + threadIdx.x) >> 5;
    int lane = threadIdx.x & 31;
    if (gw >= BATCH * SEQ) return;
    int b = gw >> 12, t = gw & (SEQ - 1);
    const float* xp = x + (size_t)(b * SEQ + t) * INPUT;
    float a0 = 0.f, a1 = 0.f, a2 = 0.f, a3 = 0.f;
    #pragma unroll
    for (int i = lane; i < INPUT; i += 32) {
        float xv = xp[i];
        a0 = fmaf(xv, __ldg(&Wu_w[0 * INPUT + i]), a0);
        a1 = fmaf(xv, __ldg(&Wu_w[1 * INPUT + i]), a1);
        a2 = fmaf(xv, __ldg(&Wu_w[2 * INPUT + i]), a2);
        a3 = fmaf(xv, __ldg(&Wu_w[3 * INPUT + i]), a3);
    }
    #pragma unroll
    for (int off = 16; off; off >>= 1) {
        a0 += __shfl_down_sync(0xffffffffu, a0, off);
        a1 += __shfl_down_sync(0xffffffffu, a1, off);
        a2 += __shfl_down_sync(0xffffffffu, a2, off);
        a3 += __shfl_down_sync(0xffffffffu, a3, off);
    }
    if (lane == 0) {
        g_u[(b * 4 + 0) * SEQ + t] = fmaxf(a0 + Wu_b[0], 0.f);
        g_u[(b * 4 + 1) * SEQ + t] = fmaxf(a1 + Wu_b[1], 0.f);
        g_u[(b * 4 + 2) * SEQ + t] = fmaxf(a2 + Wu_b[2], 0.f);
        g_u[(b * 4 + 3) * SEQ + t] = fmaxf(a3 + Wu_b[3], 0.f);
    }
}

// ---------------- 4096-pt FFT cores (radix-2, shared memory) -------------------
// Forward DIF: natural input -> bit-reversed output.
__device__ __forceinline__ void dif12(float* sre, float* sim, int tid) {
    #pragma unroll
    for (int s = LOGH - 1; s >= 0; --s) {
        int m = 1 << s;
        #pragma unroll
        for (int r = 0; r < (NH / 2) / FFT_T; ++r) {
            int k  = tid + r * FFT_T;
            int j  = k & (m - 1);
            int i0 = ((k >> s) << (s + 1)) + j;
            int i1 = i0 + m;
            float2 w = g_tw[j << (LOGH - s)];
            float ar = sre[i0], ai = sim[i0];
            float br = sre[i1], bi = sim[i1];
            sre[i0] = ar + br;
            sim[i0] = ai + bi;
            float dr = ar - br, di = ai - bi;
            sre[i1] = dr * w.x - di * w.y;
            sim[i1] = dr * w.y + di * w.x;
        }
        __syncthreads();
    }
}

// Inverse DIT (conjugate twiddles): bit-reversed input -> natural output (unscaled).
__device__ __forceinline__ void dit12_inv(float* sre, float* sim, int tid) {
    #pragma unroll
    for (int s = 0; s < LOGH; ++s) {
        int m = 1 << s;
        #pragma unroll
        for (int r = 0; r < (NH / 2) / FFT_T; ++r) {
            int k  = tid + r * FFT_T;
            int j  = k & (m - 1);
            int i0 = ((k >> s) << (s + 1)) + j;
            int i1 = i0 + m;
            float2 w = g_tw[j << (LOGH - s)];     // conj used below
            float br = sre[i1], bi = sim[i1];
            float vr = br * w.x + bi * w.y;
            float vi = bi * w.x - br * w.y;
            float ar = sre[i0], ai = sim[i0];
            sre[i0] = ar + vr;
            sim[i0] = ai + vi;
            sre[i1] = ar - vr;
            sim[i1] = ai - vi;
        }
        __syncthreads();
    }
}

// ---------------- forward real FFT of length-4096 rows (zero-padded to 8192) ---
// Output: half spectrum in BIT-REVERSED slot order (slot j holds P[rev12(j)]),
// Nyquist P[4096] stored at column NH. mode 0: g_u rows; mode 1: H rows.
__global__ void fft_fwd_kernel(const float* __restrict__ Hin, int mode) {
    __shared__ float sre[NH];
    __shared__ float sim[NH];
    int row = blockIdx.x;
    int tid = threadIdx.x;
    const float* in = mode ? (Hin + (size_t)row * SEQ) : (g_u + (size_t)row * SEQ);
    float* outre = mode ? (g_Hre + (size_t)row * KS) : (g_Ure + (size_t)row * KS);
    float* outim = mode ? (g_Him + (size_t)row * KS) : (g_Uim + (size_t)row * KS);

    const float2* in2 = (const float2*)in;   // pack z[n] = f[2n] + i f[2n+1]
    #pragma unroll
    for (int r = 0; r < NH / FFT_T; ++r) {
        int n = tid + r * FFT_T;
        if (n < SEQ / 2) { float2 v = in2[n]; sre[n] = v.x; sim[n] = v.y; }
        else             { sre[n] = 0.f;      sim[n] = 0.f; }
    }
    __syncthreads();
    dif12(sre, sim, tid);

    // Untangle in bit-reversed domain: P[k] = Xe[k] + w^k * Xo[k]
    #pragma unroll
    for (int r = 0; r < NH / FFT_T; ++r) {
        int j = tid + r * FFT_T;
        if (j == 0) {
            float zr = sre[0], zi = sim[0];
            outre[0]  = zr + zi;  outim[0]  = 0.f;   // P[0]
            outre[NH] = zr - zi;  outim[NH] = 0.f;   // P[4096] (Nyquist)
        } else {
            int k = rev12(j);
            int p = rev12(NH - k);
            float zjr = sre[j], zji = sim[j];
            float zpr = sre[p], zpi = sim[p];
            float Ar = 0.5f * (zjr + zpr), Ai = 0.5f * (zji - zpi);
            float Br = 0.5f * (zji + zpi), Bi = -0.5f * (zjr - zpr);
            float2 w = g_tw[k];
            outre[j] = Ar + w.x * Br - w.y * Bi;
            outim[j] = Ai + w.x * Bi + w.y * Br;
        }
    }
}

// ---------------- G[h,d,:] = sum_o Wh[h, d*256+o] * Hspec[o,:] ------------------
__global__ void gbuild_kernel(const float* __restrict__ Wh_w) {
    __shared__ float sA [16][65];
    __shared__ float sBr[16][68];
    __shared__ float sBi[16][68];
    int d  = blockIdx.z;
    int h0 = blockIdx.y * 64;
    int k0 = blockIdx.x * 64;
    int tid = threadIdx.x;
    int tx = tid & 15, ty = tid >> 4;
    float accr[4][4] = {}, acci[4][4] = {};

    for (int o0 = 0; o0 < ORDER; o0 += 16) {
        #pragma unroll
        for (int r = 0; r < 4; ++r) {
            int e = tid + r * 256;
            int hh = e >> 4, oo = e & 15;
            sA[oo][hh] = Wh_w[(size_t)(h0 + hh) * MSZ + d * ORDER + o0 + oo];
        }
        #pragma unroll
        for (int r = 0; r < 4; ++r) {
            int e = tid + r * 256;
            int oo = e >> 6, kk = e & 63;
            size_t src = (size_t)(o0 + oo) * KS + k0 + kk;
            sBr[oo][kk] = g_Hre[src];
            sBi[oo][kk] = g_Him[src];
        }
        __syncthreads();
        #pragma unroll
        for (int oo = 0; oo < 16; ++oo) {
            float a[4], br[4], bi[4];
            #pragma unroll
            for (int i = 0; i < 4; ++i) a[i] = sA[oo][ty * 4 + i];
            #pragma unroll
            for (int j = 0; j < 4; ++j) { br[j] = sBr[oo][tx * 4 + j]; bi[j] = sBi[oo][tx * 4 + j]; }
            #pragma unroll
            for (int i = 0; i < 4; ++i)
                #pragma unroll
                for (int j = 0; j < 4; ++j) {
                    accr[i][j] = fmaf(a[i], br[j], accr[i][j]);
                    acci[i][j] = fmaf(a[i], bi[j], acci[i][j]);
                }
        }
        __syncthreads();
    }
    #pragma unroll
    for (int i = 0; i < 4; ++i)
        #pragma unroll
        for (int j = 0; j < 4; ++j) {
            int h = h0 + ty * 4 + i;
            int k = k0 + tx * 4 + j;
            size_t dst = (size_t)(h * MD + d) * KS + k;
            g_Gre[dst] = accr[i][j];
            g_Gim[dst] = acci[i][j];
        }
}

// ---------------- hx[b,h,t] = sum_i Wh[h,1024+i]*x[b,t,i] + Wh_b[h] -------------
__global__ void hx_gemm_kernel(const float* __restrict__ x,
                               const float* __restrict__ Wh_w,
                               const float* __restrict__ Wh_b) {
    __shared__ float sA[16][65];
    __shared__ float sB[16][132];
    int b  = blockIdx.z;
    int h0 = blockIdx.y * 64;
    int t0 = blockIdx.x * 128;
    int tid = threadIdx.x;
    int tx = tid & 15, ty = tid >> 4;
    float acc[4][8] = {};

    for (int i0 = 0; i0 < INPUT; i0 += 16) {
        #pragma unroll
        for (int r = 0; r < 4; ++r) {
            int e = tid + r * 256;
            int hh = e >> 4, kk = e & 15;
            sA[kk][hh] = Wh_w[(size_t)(h0 + hh) * MSZ + MD * ORDER + i0 + kk];
        }
        #pragma unroll
        for (int r = 0; r < 8; ++r) {
            int e = tid + r * 256;
            int tt = e >> 4, kk = e & 15;
            sB[kk][tt] = x[(size_t)(b * SEQ + t0 + tt) * INPUT + i0 + kk];
        }
        __syncthreads();
        #pragma unroll
        for (int kk = 0; kk < 16; ++kk) {
            float a[4], bb[8];
            #pragma unroll
            for (int i = 0; i < 4; ++i) a[i] = sA[kk][ty * 4 + i];
            #pragma unroll
            for (int j = 0; j < 8; ++j) bb[j] = sB[kk][tx * 8 + j];
            #pragma unroll
            for (int i = 0; i < 4; ++i)
                #pragma unroll
                for (int j = 0; j < 8; ++j)
                    acc[i][j] = fmaf(a[i], bb[j], acc[i][j]);
        }
        __syncthreads();
    }
    #pragma unroll
    for (int i = 0; i < 4; ++i) {
        int h = h0 + ty * 4 + i;
        float bias = Wh_b[h];
        #pragma unroll
        for (int j = 0; j < 8; ++j) {
            int t = t0 + tx * 8 + j;
            g_hx[(size_t)(b * HID + h) * SEQ + t] = acc[i][j] + bias;
        }
    }
}

// ---------------- P = sum_d G*U ; real-iFFT ; h = relu(m + hx) (in-place) -------
__global__ void pifft_kernel() {
    __shared__ float sre[NH];
    __shared__ float sim[NH];
    __shared__ float s_nyq;
    int h = blockIdx.x >> 3;
    int b = blockIdx.x & 7;
    int tid = threadIdx.x;

    const float* Ur = g_Ure + (size_t)b * MD * KS;
    const float* Ui = g_Uim + (size_t)b * MD * KS;
    const float* Gr = g_Gre + (size_t)h * MD * KS;
    const float* Gi = g_Gim + (size_t)h * MD * KS;

    // pointwise product (bit-reversed slot order)
    #pragma unroll
    for (int r = 0; r < NH / FFT_T; ++r) {
        int j = tid + r * FFT_T;
        float pr = 0.f, pi = 0.f;
        #pragma unroll
        for (int d = 0; d < MD; ++d) {
            float ur = Ur[d * KS + j], ui = Ui[d * KS + j];
            float gr = Gr[d * KS + j], gi = Gi[d * KS + j];
            pr += ur * gr - ui * gi;
            pi += ur * gi + ui * gr;
        }
        sre[j] = pr;
        sim[j] = pi;
    }
    if (tid == 0) {
        float pn = 0.f;
        #pragma unroll
        for (int d = 0; d < MD; ++d)
            pn += Ur[d * KS + NH] * Gr[d * KS + NH] - Ui[d * KS + NH] * Gi[d * KS + NH];
        s_nyq = pn;
    }
    __syncthreads();

    // inverse pack: Z[k] = Xe[k] + i * Xo[k]   (still bit-reversed order)
    float zr[NH / FFT_T], zi[NH / FFT_T];
    #pragma unroll
    for (int r = 0; r < NH / FFT_T; ++r) {
        int j = tid + r * FFT_T;
        if (j == 0) {
            float p0 = sre[0], pn = s_nyq;
            zr[r] = 0.5f * (p0 + pn);
            zi[r] = 0.5f * (p0 - pn);
        } else {
            int k = rev12(j);
            int p = rev12(NH - k);
            float pjr = sre[j], pji = sim[j];
            float ppr = sre[p], ppi = sim[p];
            float Xer = 0.5f * (pjr + ppr), Xei = 0.5f * (pji - ppi);
            float Dr  = 0.5f * (pjr - ppr), Di  = 0.5f * (pji + ppi);
            float2 w = g_tw[k];                 // use conj(w)
            float Xor = w.x * Dr + w.y * Di;
            float Xoi = w.x * Di - w.y * Dr;
            zr[r] = Xer - Xoi;
            zi[r] = Xei + Xor;
        }
    }
    __syncthreads();
    #pragma unroll
    for (int r = 0; r < NH / FFT_T; ++r) {
        int j = tid + r * FFT_T;
        sre[j] = zr[r];
        sim[j] = zi[r];
    }
    __syncthreads();

    dit12_inv(sre, sim, tid);

    // z[n] = x[2n] + i x[2n+1]; keep first 4096 samples, fuse with hx + relu
    float* hxp = g_hx + (size_t)(b * HID + h) * SEQ;
    float2* hx2 = (float2*)hxp;
    const float inv_n = 1.0f / 4096.0f;
    #pragma unroll
    for (int r = 0; r < (SEQ / 2) / FFT_T; ++r) {
        int n = tid + r * FFT_T;
        float2 old = hx2[n];
        float2 v;
        v.x = fmaxf(fmaf(sre[n], inv_n, old.x), 0.f);
        v.y = fmaxf(fmaf(sim[n], inv_n, old.y), 0.f);
        hx2[n] = v;
    }
}

// ---------------- transpose [b][h][t] -> out [b][t][h] --------------------------
__global__ void transpose_kernel(float* __restrict__ out) {
    __shared__ float tile[32][33];
    int b  = blockIdx.z;
    int h0 = blockIdx.y * 32;
    int t0 = blockIdx.x * 32;
    int tx = threadIdx.x, ty = threadIdx.y;
    #pragma unroll
    for (int r = 0; r < 32; r += 8)
        tile[ty + r][tx] = g_hx[(size_t)(b * HID + h0 + ty + r) * SEQ + t0 + tx];
    __syncthreads();
    #pragma unroll
    for (int r = 0; r < 32; r += 8)
        out[(size_t)(b * SEQ + t0 + ty + r) * HID + h0 + tx] = tile[tx][ty + r];
}

// ---------------- h[:, -1, :] appended after h -----------------------------------
__global__ void last_kernel(float* __restrict__ out) {
    int i = blockIdx.x * blockDim.x + threadIdx.x;
    if (i < BATCH * HID)
        out[(size_t)BATCH * SEQ * HID + i] = g_hx[(size_t)i * SEQ + (SEQ - 1)];
}

// ---------------- launch ----------------------------------------------------------
extern "C" void kernel_launch(void* const* d_in, const int* in_sizes, int n_in,
                              void* d_out, int out_size) {
    const float* x    = (const float*)d_in[0];
    const float* Wu_w = (const float*)d_in[1];
    const float* Wu_b = (const float*)d_in[2];
    const float* Wh_w = (const float*)d_in[3];
    const float* Wh_b = (const float*)d_in[4];
    const float* H    = (const float*)d_in[5];
    float* out = (float*)d_out;

    twiddle_kernel<<<8, 512>>>();
    u_kernel<<<(BATCH * SEQ * 32) / 256, 256>>>(x, Wu_w, Wu_b);

    fft_fwd_kernel<<<32,    FFT_T>>>(nullptr, 0);   // u spectra (half, bitrev)
    fft_fwd_kernel<<<ORDER, FFT_T>>>(H, 1);         // H spectra (half, bitrev)

    gbuild_kernel<<<dim3(KS / 64, HID / 64, MD), 256>>>(Wh_w);
    hx_gemm_kernel<<<dim3(SEQ / 128, HID / 64, BATCH), 256>>>(x, Wh_w, Wh_b);

    pifft_kernel<<<HID * BATCH, FFT_T>>>();

    transpose_kernel<<<dim3(SEQ / 32, HID / 32, BATCH), dim3(32, 8)>>>(out);
    if (out_size >= BATCH * SEQ * HID + BATCH * HID)
        last_kernel<<<8, 512>>>(out);
}